// round 2
// baseline (speedup 1.0000x reference)
#include <cuda_runtime.h>
#include <math.h>

// Problem constants
#define B_   2
#define S_   4096
#define H_   2048
#define NH_  16
#define D_   128
#define CH_  64
#define NC_  64          // S_/CH_
#define M_   (B_*S_)     // 8192

// ---------------------------------------------------------------------------
// Scratch (device globals -- allocation-free per harness rules)
// ---------------------------------------------------------------------------
__device__ float g_q[(size_t)B_*NH_*S_*D_];     // [bh][s][d]
__device__ float g_k[(size_t)B_*NH_*S_*D_];
__device__ float g_u[(size_t)B_*NH_*S_*D_];
__device__ float g_vraw[(size_t)M_*H_];         // [row][col]
__device__ float g_braw[(size_t)M_*H_];
__device__ float g_o[(size_t)M_*H_];            // attn in [b*S+s][h*D+d] layout
__device__ float g_P[(size_t)B_*NH_*NC_*D_*D_]; // per-chunk outer products -> exclusive prefix

// ---------------------------------------------------------------------------
// Generic 128x128x16 fp32 SGEMM, row-major A[M,K] @ B[K,N] -> C
// MODE 0: flat row-major C[M,N]
// MODE 1: head layout: out[((b*NH+h)*S + s)*D + d]  (requires N=2048, BN=128)
// ---------------------------------------------------------------------------
template<int MODE>
__global__ __launch_bounds__(256) void sgemm128(
    const float* __restrict__ A, const float* __restrict__ Bm,
    float* __restrict__ C, int M, int N, int K)
{
    __shared__ float As[16][128];   // transposed A tile: As[k][m]
    __shared__ float Bs[16][128];

    const int tid = threadIdx.x;
    const int bx = blockIdx.x, by = blockIdx.y;
    const int tx4 = (tid & 15) * 4;
    const int ty4 = (tid >> 4) * 4;

    float acc[8][8];
#pragma unroll
    for (int i = 0; i < 8; i++)
#pragma unroll
        for (int j = 0; j < 8; j++) acc[i][j] = 0.f;

    const float* Abase = A + (size_t)(by * 128) * K;
    const float* Bbase = Bm + bx * 128;

    float4 pa[2], pb[2];
    // prefetch tile 0
#pragma unroll
    for (int p = 0; p < 2; p++) {
        int v = tid + p * 256;
        int r = v >> 2, c4 = (v & 3) * 4;
        pa[p] = *(const float4*)(Abase + (size_t)r * K + c4);
        int kk = v >> 5, cb = (v & 31) * 4;
        pb[p] = *(const float4*)(Bbase + (size_t)kk * N + cb);
    }

    const int KT = K / 16;
    for (int t = 0; t < KT; t++) {
        // commit prefetched tile to smem
#pragma unroll
        for (int p = 0; p < 2; p++) {
            int v = tid + p * 256;
            int r = v >> 2, c4 = (v & 3) * 4;
            As[c4 + 0][r] = pa[p].x; As[c4 + 1][r] = pa[p].y;
            As[c4 + 2][r] = pa[p].z; As[c4 + 3][r] = pa[p].w;
            int kk = v >> 5, cb = (v & 31) * 4;
            *(float4*)&Bs[kk][cb] = pb[p];
        }
        __syncthreads();
        if (t + 1 < KT) {
            int k0 = (t + 1) * 16;
#pragma unroll
            for (int p = 0; p < 2; p++) {
                int v = tid + p * 256;
                int r = v >> 2, c4 = (v & 3) * 4;
                pa[p] = *(const float4*)(Abase + (size_t)r * K + k0 + c4);
                int kk = v >> 5, cb = (v & 31) * 4;
                pb[p] = *(const float4*)(Bbase + (size_t)(k0 + kk) * N + cb);
            }
        }
#pragma unroll
        for (int kk = 0; kk < 16; kk++) {
            float4 a0 = *(const float4*)&As[kk][ty4];
            float4 a1 = *(const float4*)&As[kk][64 + ty4];
            float4 b0 = *(const float4*)&Bs[kk][tx4];
            float4 b1 = *(const float4*)&Bs[kk][64 + tx4];
            float av[8] = {a0.x, a0.y, a0.z, a0.w, a1.x, a1.y, a1.z, a1.w};
            float bv[8] = {b0.x, b0.y, b0.z, b0.w, b1.x, b1.y, b1.z, b1.w};
#pragma unroll
            for (int i = 0; i < 8; i++)
#pragma unroll
                for (int j = 0; j < 8; j++)
                    acc[i][j] += av[i] * bv[j];
        }
        __syncthreads();
    }

    // epilogue
#pragma unroll
    for (int i = 0; i < 8; i++) {
        int rl = (i < 4) ? (ty4 + i) : (64 + ty4 + i - 4);
        int gr = by * 128 + rl;
        float4 v0 = make_float4(acc[i][0], acc[i][1], acc[i][2], acc[i][3]);
        float4 v1 = make_float4(acc[i][4], acc[i][5], acc[i][6], acc[i][7]);
        if (MODE == 0) {
            float* p = C + (size_t)gr * N + bx * 128;
            *(float4*)(p + tx4) = v0;
            *(float4*)(p + 64 + tx4) = v1;
        } else {
            int b = gr >> 12;           // /S_
            int s = gr & (S_ - 1);
            int h = bx;                 // BN==D_, N==2048
            float* p = C + ((size_t)(b * NH_ + h) * S_ + s) * D_;
            *(float4*)(p + tx4) = v0;
            *(float4*)(p + 64 + tx4) = v1;
        }
    }
}

// ---------------------------------------------------------------------------
// u = sigmoid(braw) * vraw, written to head layout [bh][s][d]
// ---------------------------------------------------------------------------
__global__ __launch_bounds__(256) void ewise_u(
    const float* __restrict__ vr, const float* __restrict__ br,
    float* __restrict__ u)
{
    int v = blockIdx.x * 256 + threadIdx.x;      // float4 index, total M_*H_/4
    int row = v >> 9;                            // H_/4 = 512 float4 per row
    int col = (v & 511) * 4;
    float4 vv = *(const float4*)(vr + (size_t)row * H_ + col);
    float4 bb = *(const float4*)(br + (size_t)row * H_ + col);
    float4 r;
    r.x = vv.x / (1.f + expf(-bb.x));
    r.y = vv.y / (1.f + expf(-bb.y));
    r.z = vv.z / (1.f + expf(-bb.z));
    r.w = vv.w / (1.f + expf(-bb.w));
    int b = row >> 12, s = row & (S_ - 1);
    int h = col >> 7, d = col & 127;
    *(float4*)(u + ((size_t)(b * NH_ + h) * S_ + s) * D_ + d) = r;
}

// ---------------------------------------------------------------------------
// Per-chunk local work (fully parallel over 2048 chunks):
//   att = tril(q k^T), o_intra = att @ u, P = u^T k
// smem padded stride 132 to break bank conflicts on row-gather reads.
// ---------------------------------------------------------------------------
#define STP 132
#define CL_SMEM ((3 * 64 * STP + 64 * 65) * 4)

__global__ __launch_bounds__(256) void chunk_local(
    const float* __restrict__ q, const float* __restrict__ k,
    const float* __restrict__ u, float* __restrict__ o,
    float* __restrict__ P)
{
    extern __shared__ float sm[];
    float* sq  = sm;
    float* sk  = sm + 64 * STP;
    float* su  = sm + 2 * 64 * STP;
    float* att = sm + 3 * 64 * STP;   // [64][65]

    const int n = blockIdx.x, bh = blockIdx.y;
    const int tid = threadIdx.x;
    const size_t gbase = ((size_t)bh * S_ + n * 64) * D_;

    for (int v = tid; v < 64 * 32; v += 256) {
        int r = v >> 5, c4 = (v & 31) * 4;
        *(float4*)&sq[r * STP + c4] = *(const float4*)(q + gbase + r * 128 + c4);
        *(float4*)&sk[r * STP + c4] = *(const float4*)(k + gbase + r * 128 + c4);
        *(float4*)&su[r * STP + c4] = *(const float4*)(u + gbase + r * 128 + c4);
    }
    __syncthreads();

    // (a) att = tril(q k^T), diagonal included
    {
        int i0 = (tid >> 4) * 4, j0 = (tid & 15) * 4;
        float a[4][4] = {};
        for (int e = 0; e < 128; e += 4) {
            float4 qv[4], kv[4];
#pragma unroll
            for (int r = 0; r < 4; r++) qv[r] = *(const float4*)&sq[(i0 + r) * STP + e];
#pragma unroll
            for (int c = 0; c < 4; c++) kv[c] = *(const float4*)&sk[(j0 + c) * STP + e];
#pragma unroll
            for (int r = 0; r < 4; r++)
#pragma unroll
                for (int c = 0; c < 4; c++)
                    a[r][c] += qv[r].x * kv[c].x + qv[r].y * kv[c].y
                             + qv[r].z * kv[c].z + qv[r].w * kv[c].w;
        }
#pragma unroll
        for (int r = 0; r < 4; r++)
#pragma unroll
            for (int c = 0; c < 4; c++)
                att[(i0 + r) * 65 + (j0 + c)] = (j0 + c <= i0 + r) ? a[r][c] : 0.f;
    }
    __syncthreads();

    // (b) o_intra = att @ u
    {
        int i0 = (tid >> 4) * 4, d0 = (tid & 15) * 8;
        float acc[4][8] = {};
        for (int j = 0; j < 64; j++) {
            float am[4];
#pragma unroll
            for (int r = 0; r < 4; r++) am[r] = att[(i0 + r) * 65 + j];
            float4 u0 = *(const float4*)&su[j * STP + d0];
            float4 u1 = *(const float4*)&su[j * STP + d0 + 4];
            float uu[8] = {u0.x, u0.y, u0.z, u0.w, u1.x, u1.y, u1.z, u1.w};
#pragma unroll
            for (int r = 0; r < 4; r++)
#pragma unroll
                for (int c = 0; c < 8; c++)
                    acc[r][c] += am[r] * uu[c];
        }
        int b = bh >> 4, h = bh & 15;
#pragma unroll
        for (int r = 0; r < 4; r++) {
            float* p = o + (size_t)(b * S_ + n * 64 + i0 + r) * H_ + h * 128 + d0;
            *(float4*)(p)     = make_float4(acc[r][0], acc[r][1], acc[r][2], acc[r][3]);
            *(float4*)(p + 4) = make_float4(acc[r][4], acc[r][5], acc[r][6], acc[r][7]);
        }
    }

    // (c) P[d][e] = sum_i u[i][d] * k[i][e]
    {
        int d0 = (tid >> 4) * 8, e0 = (tid & 15) * 8;
        float acc[8][8] = {};
        for (int i = 0; i < 64; i++) {
            float4 ua = *(const float4*)&su[i * STP + d0];
            float4 ub = *(const float4*)&su[i * STP + d0 + 4];
            float4 ka = *(const float4*)&sk[i * STP + e0];
            float4 kb = *(const float4*)&sk[i * STP + e0 + 4];
            float uu[8] = {ua.x, ua.y, ua.z, ua.w, ub.x, ub.y, ub.z, ub.w};
            float kk[8] = {ka.x, ka.y, ka.z, ka.w, kb.x, kb.y, kb.z, kb.w};
#pragma unroll
            for (int r = 0; r < 8; r++)
#pragma unroll
                for (int c = 0; c < 8; c++)
                    acc[r][c] += uu[r] * kk[c];
        }
        float* Pp = P + ((size_t)bh * NC_ + n) * (D_ * D_);
#pragma unroll
        for (int r = 0; r < 8; r++) {
            float* p = Pp + (size_t)(d0 + r) * 128 + e0;
            *(float4*)(p)     = make_float4(acc[r][0], acc[r][1], acc[r][2], acc[r][3]);
            *(float4*)(p + 4) = make_float4(acc[r][4], acc[r][5], acc[r][6], acc[r][7]);
        }
    }
}

// ---------------------------------------------------------------------------
// Sequential-over-chunks exclusive prefix sum of P per (bh); writes final
// state to output tail. grid = B*NH*8, each CTA handles 2048 of the 16384
// state elements; each thread owns 8 consecutive floats.
// ---------------------------------------------------------------------------
__global__ __launch_bounds__(256) void prefix_state(
    float* __restrict__ P, float* __restrict__ out_state)
{
    int bh = blockIdx.x >> 3;
    int part = blockIdx.x & 7;
    int idx = part * 2048 + threadIdx.x * 8;
    float acc[8] = {0, 0, 0, 0, 0, 0, 0, 0};
    float* base = P + (size_t)bh * NC_ * (D_ * D_) + idx;
    for (int nn = 0; nn < NC_; nn++) {
        float* p = base + (size_t)nn * (D_ * D_);
        float4 p0 = *(float4*)(p);
        float4 p1 = *(float4*)(p + 4);
        *(float4*)(p)     = make_float4(acc[0], acc[1], acc[2], acc[3]);
        *(float4*)(p + 4) = make_float4(acc[4], acc[5], acc[6], acc[7]);
        acc[0] += p0.x; acc[1] += p0.y; acc[2] += p0.z; acc[3] += p0.w;
        acc[4] += p1.x; acc[5] += p1.y; acc[6] += p1.z; acc[7] += p1.w;
    }
    float* q = out_state + (size_t)bh * (D_ * D_) + idx;
    *(float4*)(q)     = make_float4(acc[0], acc[1], acc[2], acc[3]);
    *(float4*)(q + 4) = make_float4(acc[4], acc[5], acc[6], acc[7]);
}

// ---------------------------------------------------------------------------
// Inter-chunk contribution: o[i][d] += sum_e q[i][e] * S_n[d][e]
// ---------------------------------------------------------------------------
#define IN_SMEM ((64 * STP + 128 * STP) * 4)

__global__ __launch_bounds__(256) void inter_chunk(
    const float* __restrict__ q, const float* __restrict__ P,
    float* __restrict__ o)
{
    extern __shared__ float sm[];
    float* sq = sm;              // [64][STP]
    float* sS = sm + 64 * STP;   // [128][STP]

    const int n = blockIdx.x, bh = blockIdx.y;
    const int tid = threadIdx.x;
    const size_t qbase = ((size_t)bh * S_ + n * 64) * D_;
    const float* Sp = P + ((size_t)bh * NC_ + n) * (D_ * D_);

    for (int v = tid; v < 64 * 32; v += 256) {
        int r = v >> 5, c4 = (v & 31) * 4;
        *(float4*)&sq[r * STP + c4] = *(const float4*)(q + qbase + r * 128 + c4);
    }
    for (int v = tid; v < 128 * 32; v += 256) {
        int r = v >> 5, c4 = (v & 31) * 4;
        *(float4*)&sS[r * STP + c4] = *(const float4*)(Sp + (size_t)r * 128 + c4);
    }
    __syncthreads();

    int i0 = (tid >> 4) * 4, d0 = (tid & 15) * 8;
    float acc[4][8] = {};
    for (int e = 0; e < 128; e += 4) {
        float4 qv[4];
#pragma unroll
        for (int r = 0; r < 4; r++) qv[r] = *(const float4*)&sq[(i0 + r) * STP + e];
#pragma unroll
        for (int c = 0; c < 8; c++) {
            float4 sv = *(const float4*)&sS[(d0 + c) * STP + e];
#pragma unroll
            for (int r = 0; r < 4; r++)
                acc[r][c] += qv[r].x * sv.x + qv[r].y * sv.y
                           + qv[r].z * sv.z + qv[r].w * sv.w;
        }
    }
    int b = bh >> 4, h = bh & 15;
#pragma unroll
    for (int r = 0; r < 4; r++) {
        float* p = o + (size_t)(b * S_ + n * 64 + i0 + r) * H_ + h * 128 + d0;
        float4 c0 = *(float4*)(p);
        float4 c1 = *(float4*)(p + 4);
        c0.x += acc[r][0]; c0.y += acc[r][1]; c0.z += acc[r][2]; c0.w += acc[r][3];
        c1.x += acc[r][4]; c1.y += acc[r][5]; c1.z += acc[r][6]; c1.w += acc[r][7];
        *(float4*)(p)     = c0;
        *(float4*)(p + 4) = c1;
    }
}

// ---------------------------------------------------------------------------
// Launch
// ---------------------------------------------------------------------------
extern "C" void kernel_launch(void* const* d_in, const int* in_sizes, int n_in,
                              void* d_out, int out_size)
{
    (void)in_sizes; (void)n_in; (void)out_size;
    const float* x  = (const float*)d_in[0];
    const float* Wq = (const float*)d_in[1];
    const float* Wk = (const float*)d_in[2];
    const float* Wv = (const float*)d_in[3];
    const float* Wb = (const float*)d_in[4];
    const float* Wo = (const float*)d_in[5];
    float* out = (float*)d_out;
    float* out_state = out + (size_t)M_ * H_;

    float *pq, *pk, *pu, *pvr, *pbr, *po, *pP;
    cudaGetSymbolAddress((void**)&pq,  g_q);
    cudaGetSymbolAddress((void**)&pk,  g_k);
    cudaGetSymbolAddress((void**)&pu,  g_u);
    cudaGetSymbolAddress((void**)&pvr, g_vraw);
    cudaGetSymbolAddress((void**)&pbr, g_braw);
    cudaGetSymbolAddress((void**)&po,  g_o);
    cudaGetSymbolAddress((void**)&pP,  g_P);

    cudaFuncSetAttribute(chunk_local, cudaFuncAttributeMaxDynamicSharedMemorySize, CL_SMEM);
    cudaFuncSetAttribute(inter_chunk, cudaFuncAttributeMaxDynamicSharedMemorySize, IN_SMEM);

    dim3 gg(H_ / 128, M_ / 128);   // (16, 64)

    sgemm128<1><<<gg, 256>>>(x, Wq, pq,  M_, H_, H_);
    sgemm128<1><<<gg, 256>>>(x, Wk, pk,  M_, H_, H_);
    sgemm128<0><<<gg, 256>>>(x, Wv, pvr, M_, H_, H_);
    sgemm128<0><<<gg, 256>>>(x, Wb, pbr, M_, H_, H_);

    ewise_u<<<(M_ * H_ / 4) / 256, 256>>>(pvr, pbr, pu);

    dim3 gc(NC_, B_ * NH_);        // (64, 32)
    chunk_local<<<gc, 256, CL_SMEM>>>(pq, pk, pu, po, pP);
    prefix_state<<<B_ * NH_ * 8, 256>>>(pP, out_state);
    inter_chunk<<<gc, 256, IN_SMEM>>>(pq, pP, po);

    sgemm128<0><<<gg, 256>>>(po, Wo, out, M_, H_, H_);
}

// round 5
// speedup vs baseline: 2.2344x; 2.2344x over previous
#include <cuda_runtime.h>
#include <cuda_bf16.h>
#include <math.h>
#include <stdint.h>

// Problem constants
#define B_   2
#define S_   4096
#define H_   2048
#define NH_  16
#define D_   128
#define NC_  64          // S_/64
#define M_   (B_*S_)     // 8192
#define KTOT 2048

// ---------------------------------------------------------------------------
// Scratch (device globals -- allocation-free per harness rules)
// ---------------------------------------------------------------------------
__device__ float g_q[(size_t)B_*NH_*S_*D_];     // [bh][s][d]
__device__ float g_k[(size_t)B_*NH_*S_*D_];
__device__ float g_u[(size_t)B_*NH_*S_*D_];
__device__ float g_vraw[(size_t)M_*H_];         // [row][col]
__device__ float g_braw[(size_t)M_*H_];
__device__ float g_o[(size_t)M_*H_];            // attn in [b*S+s][h*D+d] layout
__device__ float g_P[(size_t)B_*NH_*NC_*D_*D_]; // per-chunk outer products -> excl prefix
__device__ __nv_bfloat16 g_xh[(size_t)M_*H_];   // split bf16 activations
__device__ __nv_bfloat16 g_xl[(size_t)M_*H_];
__device__ __nv_bfloat16 g_oh[(size_t)M_*H_];
__device__ __nv_bfloat16 g_ol[(size_t)M_*H_];
__device__ __nv_bfloat16 g_Wth[5ull*H_*H_];     // transposed weights [N][K], hi
__device__ __nv_bfloat16 g_Wtl[5ull*H_*H_];     // lo

// ---------------------------------------------------------------------------
// PTX helpers (ALL baseline sm_80+ instructions -- no arch-specific features,
// since the harness compiles to plain .target sm_100)
// ---------------------------------------------------------------------------
__device__ __forceinline__ uint32_t s2u(const void* p) {
    uint32_t a;
    asm("{ .reg .u64 t; cvta.to.shared.u64 t, %1; cvt.u32.u64 %0, t; }"
        : "=r"(a) : "l"(p));
    return a;
}

#define CPA(dst, src) \
    asm volatile("cp.async.cg.shared.global [%0], [%1], 16;" :: "r"(dst), "l"(src))
#define CPA_COMMIT() asm volatile("cp.async.commit_group;" ::: "memory")

__device__ __forceinline__ void ldmA(uint32_t (&a)[4], uint32_t addr) {
    asm volatile("ldmatrix.sync.aligned.m8n8.x4.shared.b16 {%0,%1,%2,%3}, [%4];"
                 : "=r"(a[0]), "=r"(a[1]), "=r"(a[2]), "=r"(a[3]) : "r"(addr));
}
__device__ __forceinline__ void ldmB(uint32_t (&b)[2], uint32_t addr) {
    asm volatile("ldmatrix.sync.aligned.m8n8.x2.shared.b16 {%0,%1}, [%2];"
                 : "=r"(b[0]), "=r"(b[1]) : "r"(addr));
}
__device__ __forceinline__ void mma16816(float (&c)[4], const uint32_t (&a)[4],
                                         const uint32_t (&b)[2]) {
    asm volatile(
        "mma.sync.aligned.m16n8k16.row.col.f32.bf16.bf16.f32 "
        "{%0,%1,%2,%3}, {%4,%5,%6,%7}, {%8,%9}, {%0,%1,%2,%3};"
        : "+f"(c[0]), "+f"(c[1]), "+f"(c[2]), "+f"(c[3])
        : "r"(a[0]), "r"(a[1]), "r"(a[2]), "r"(a[3]), "r"(b[0]), "r"(b[1]));
}

// ---------------------------------------------------------------------------
// bf16 split-precision mma.sync GEMM:
//   C[M,2048] = A @ W;  A = Ahi+Alo (bf16, [m][k]),  W^T = Bhi+Blo ([n][k])
//   3 passes: Ahi*Bhi + Ahi*Blo + Alo*Bhi, fp32 accumulate.
// CTA tile 128x128, 8 warps (4 M x 2 N, warp tile 32x64), BK=32,
// cp.async double buffered. SMEM rows padded to 80B (conflict-free ldmatrix).
// MODE 0: flat row-major C[M,N]; MODE 1: head layout out[((b*NH+h)*S+s)*D+d]
// ---------------------------------------------------------------------------
#define BKC 32
#define KT_ (KTOT / BKC)          // 64 iterations
#define PITCH 80                  // bytes per 32-bf16 row
#define MAT_BYTES (128 * PITCH)   // 10240 per matrix
#define STAGE_BYTES (4 * MAT_BYTES)  // Ah, Al, Bh, Bl
#define GEMM_SMEM (2 * STAGE_BYTES)  // 81920

template<int MODE>
__global__ __launch_bounds__(256, 2) void tcgemm(
    const __nv_bfloat16* __restrict__ Ah, const __nv_bfloat16* __restrict__ Al,
    const __nv_bfloat16* __restrict__ Bh, const __nv_bfloat16* __restrict__ Bl,
    float* __restrict__ C)
{
    extern __shared__ char smem[];
    const uint32_t sbase = s2u(smem);
    const int tid = threadIdx.x;
    const int lane = tid & 31, wid = tid >> 5;
    const int wm = wid >> 1, wn = wid & 1;
    const int bx = blockIdx.x;   // N tile 0..15
    const int by = blockIdx.y;   // M tile 0..63

    const __nv_bfloat16* Aph = Ah + (size_t)(by * 128) * KTOT;
    const __nv_bfloat16* Apl = Al + (size_t)(by * 128) * KTOT;
    const __nv_bfloat16* Bph = Bh + (size_t)(bx * 128) * KTOT;
    const __nv_bfloat16* Bpl = Bl + (size_t)(bx * 128) * KTOT;

    float acc[2][8][4];
#pragma unroll
    for (int mi = 0; mi < 2; mi++)
#pragma unroll
        for (int ni = 0; ni < 8; ni++)
#pragma unroll
            for (int j = 0; j < 4; j++) acc[mi][ni][j] = 0.f;

    // stage loader: 2 x (r,c) chunks per thread per matrix
    auto load_stage = [&](int k0, int stg) {
        uint32_t sb = sbase + stg * STAGE_BYTES;
#pragma unroll
        for (int i = 0; i < 2; i++) {
            int v = tid + i * 256;
            int r = v >> 2, c = v & 3;
            uint32_t so = r * PITCH + c * 16;
            size_t go = (size_t)r * KTOT + k0 + c * 8;
            CPA(sb + so,                 Aph + go);
            CPA(sb + MAT_BYTES + so,     Apl + go);
            CPA(sb + 2 * MAT_BYTES + so, Bph + go);
            CPA(sb + 3 * MAT_BYTES + so, Bpl + go);
        }
        CPA_COMMIT();
    };

    load_stage(0, 0);

    const int arow = lane & 15, achk = lane >> 4;
    const int brow = lane & 7,  bchk = (lane >> 3) & 1;

    for (int t = 0; t < KT_; t++) {
        if (t + 1 < KT_) load_stage((t + 1) * BKC, (t + 1) & 1);
        if (t + 1 < KT_) asm volatile("cp.async.wait_group 1;" ::: "memory");
        else             asm volatile("cp.async.wait_group 0;" ::: "memory");
        __syncthreads();

        const uint32_t ab = sbase + (t & 1) * STAGE_BYTES;           // A hi
        const uint32_t bb = ab + 2 * MAT_BYTES;                       // B hi
#pragma unroll
        for (int ks = 0; ks < 2; ks++) {
            uint32_t ah[2][4], al[2][4];
#pragma unroll
            for (int mi = 0; mi < 2; mi++) {
                uint32_t ra = ab + (uint32_t)(wm * 32 + mi * 16 + arow) * PITCH
                            + ks * 32 + achk * 16;
                ldmA(ah[mi], ra);
                ldmA(al[mi], ra + MAT_BYTES);
            }
#pragma unroll
            for (int ni = 0; ni < 8; ni++) {
                uint32_t rb = bb + (uint32_t)(wn * 64 + ni * 8 + brow) * PITCH
                            + ks * 32 + bchk * 16;
                uint32_t bh[2], bl[2];
                ldmB(bh, rb);
                ldmB(bl, rb + MAT_BYTES);
#pragma unroll
                for (int mi = 0; mi < 2; mi++) {
                    mma16816(acc[mi][ni], ah[mi], bh);
                    mma16816(acc[mi][ni], ah[mi], bl);
                    mma16816(acc[mi][ni], al[mi], bh);
                }
            }
        }
        __syncthreads();
    }

    // epilogue
#pragma unroll
    for (int mi = 0; mi < 2; mi++) {
        int r0 = by * 128 + wm * 32 + mi * 16 + (lane >> 2);
#pragma unroll
        for (int ni = 0; ni < 8; ni++) {
            int cc = wn * 64 + ni * 8 + (lane & 3) * 2;
            float2 lo = make_float2(acc[mi][ni][0], acc[mi][ni][1]);
            float2 hi = make_float2(acc[mi][ni][2], acc[mi][ni][3]);
            if (MODE == 0) {
                float* p = C + (size_t)r0 * H_ + bx * 128 + cc;
                *(float2*)p = lo;
                *(float2*)(p + 8 * H_) = hi;
            } else {
                int b = r0 >> 12, s = r0 & (S_ - 1);
                size_t base = ((size_t)(b * NH_ + bx) * S_ + s) * D_ + cc;
                *(float2*)(C + base) = lo;
                *(float2*)(C + base + 8 * D_) = hi;
            }
        }
    }
}

// ---------------------------------------------------------------------------
// Split fp32 -> bf16 hi/lo (same layout)
// ---------------------------------------------------------------------------
struct alignas(8) bf4 { __nv_bfloat16 v[4]; };

__global__ __launch_bounds__(256) void split_convert(
    const float* __restrict__ in, __nv_bfloat16* __restrict__ hi,
    __nv_bfloat16* __restrict__ lo)
{
    size_t v = (size_t)blockIdx.x * 256 + threadIdx.x;
    float4 x = *(const float4*)(in + v * 4);
    bf4 h, l;
    float xs[4] = {x.x, x.y, x.z, x.w};
#pragma unroll
    for (int i = 0; i < 4; i++) {
        __nv_bfloat16 hh = __float2bfloat16(xs[i]);
        h.v[i] = hh;
        l.v[i] = __float2bfloat16(xs[i] - __bfloat162float(hh));
    }
    *(bf4*)(hi + v * 4) = h;
    *(bf4*)(lo + v * 4) = l;
}

// ---------------------------------------------------------------------------
// Weight transpose + split: Wt[n][k] = W[k][n] as bf16 hi/lo
// ---------------------------------------------------------------------------
__global__ __launch_bounds__(256) void transpose_split(
    const float* __restrict__ in, __nv_bfloat16* __restrict__ outh,
    __nv_bfloat16* __restrict__ outl)
{
    __shared__ float t[32][33];
    int x = blockIdx.x * 32 + threadIdx.x;
    int y = blockIdx.y * 32 + threadIdx.y;
#pragma unroll
    for (int i = 0; i < 32; i += 8)
        t[threadIdx.y + i][threadIdx.x] = in[(size_t)(y + i) * H_ + x];
    __syncthreads();
    x = blockIdx.y * 32 + threadIdx.x;
    y = blockIdx.x * 32 + threadIdx.y;
#pragma unroll
    for (int i = 0; i < 32; i += 8) {
        float val = t[threadIdx.x][threadIdx.y + i];
        __nv_bfloat16 hh = __float2bfloat16(val);
        outh[(size_t)(y + i) * H_ + x] = hh;
        outl[(size_t)(y + i) * H_ + x] = __float2bfloat16(val - __bfloat162float(hh));
    }
}

// ---------------------------------------------------------------------------
// u = sigmoid(braw) * vraw, written to head layout [bh][s][d]
// ---------------------------------------------------------------------------
__global__ __launch_bounds__(256) void ewise_u(
    const float* __restrict__ vr, const float* __restrict__ br,
    float* __restrict__ u)
{
    int v = blockIdx.x * 256 + threadIdx.x;
    int row = v >> 9;
    int col = (v & 511) * 4;
    float4 vv = *(const float4*)(vr + (size_t)row * H_ + col);
    float4 bb = *(const float4*)(br + (size_t)row * H_ + col);
    float4 r;
    r.x = vv.x / (1.f + expf(-bb.x));
    r.y = vv.y / (1.f + expf(-bb.y));
    r.z = vv.z / (1.f + expf(-bb.z));
    r.w = vv.w / (1.f + expf(-bb.w));
    int b = row >> 12, s = row & (S_ - 1);
    int h = col >> 7, d = col & 127;
    *(float4*)(u + ((size_t)(b * NH_ + h) * S_ + s) * D_ + d) = r;
}

// ---------------------------------------------------------------------------
// Per-chunk local work: att = tril(q k^T), o_intra = att @ u, P = u^T k
// ---------------------------------------------------------------------------
#define STP 132
#define CL_SMEM ((3 * 64 * STP + 64 * 65) * 4)

__global__ __launch_bounds__(256) void chunk_local(
    const float* __restrict__ q, const float* __restrict__ k,
    const float* __restrict__ u, float* __restrict__ o,
    float* __restrict__ P)
{
    extern __shared__ float sm[];
    float* sq  = sm;
    float* sk  = sm + 64 * STP;
    float* su  = sm + 2 * 64 * STP;
    float* att = sm + 3 * 64 * STP;   // [64][65]

    const int n = blockIdx.x, bh = blockIdx.y;
    const int tid = threadIdx.x;
    const size_t gbase = ((size_t)bh * S_ + n * 64) * D_;

    for (int v = tid; v < 64 * 32; v += 256) {
        int r = v >> 5, c4 = (v & 31) * 4;
        *(float4*)&sq[r * STP + c4] = *(const float4*)(q + gbase + r * 128 + c4);
        *(float4*)&sk[r * STP + c4] = *(const float4*)(k + gbase + r * 128 + c4);
        *(float4*)&su[r * STP + c4] = *(const float4*)(u + gbase + r * 128 + c4);
    }
    __syncthreads();

    {
        int i0 = (tid >> 4) * 4, j0 = (tid & 15) * 4;
        float a[4][4] = {};
        for (int e = 0; e < 128; e += 4) {
            float4 qv[4], kv[4];
#pragma unroll
            for (int r = 0; r < 4; r++) qv[r] = *(const float4*)&sq[(i0 + r) * STP + e];
#pragma unroll
            for (int c = 0; c < 4; c++) kv[c] = *(const float4*)&sk[(j0 + c) * STP + e];
#pragma unroll
            for (int r = 0; r < 4; r++)
#pragma unroll
                for (int c = 0; c < 4; c++)
                    a[r][c] += qv[r].x * kv[c].x + qv[r].y * kv[c].y
                             + qv[r].z * kv[c].z + qv[r].w * kv[c].w;
        }
#pragma unroll
        for (int r = 0; r < 4; r++)
#pragma unroll
            for (int c = 0; c < 4; c++)
                att[(i0 + r) * 65 + (j0 + c)] = (j0 + c <= i0 + r) ? a[r][c] : 0.f;
    }
    __syncthreads();

    {
        int i0 = (tid >> 4) * 4, d0 = (tid & 15) * 8;
        float acc[4][8] = {};
        for (int j = 0; j < 64; j++) {
            float am[4];
#pragma unroll
            for (int r = 0; r < 4; r++) am[r] = att[(i0 + r) * 65 + j];
            float4 u0 = *(const float4*)&su[j * STP + d0];
            float4 u1 = *(const float4*)&su[j * STP + d0 + 4];
            float uu[8] = {u0.x, u0.y, u0.z, u0.w, u1.x, u1.y, u1.z, u1.w};
#pragma unroll
            for (int r = 0; r < 4; r++)
#pragma unroll
                for (int c = 0; c < 8; c++)
                    acc[r][c] += am[r] * uu[c];
        }
        int b = bh >> 4, h = bh & 15;
#pragma unroll
        for (int r = 0; r < 4; r++) {
            float* p = o + (size_t)(b * S_ + n * 64 + i0 + r) * H_ + h * 128 + d0;
            *(float4*)(p)     = make_float4(acc[r][0], acc[r][1], acc[r][2], acc[r][3]);
            *(float4*)(p + 4) = make_float4(acc[r][4], acc[r][5], acc[r][6], acc[r][7]);
        }
    }

    {
        int d0 = (tid >> 4) * 8, e0 = (tid & 15) * 8;
        float acc[8][8] = {};
        for (int i = 0; i < 64; i++) {
            float4 ua = *(const float4*)&su[i * STP + d0];
            float4 ub = *(const float4*)&su[i * STP + d0 + 4];
            float4 ka = *(const float4*)&sk[i * STP + e0];
            float4 kb = *(const float4*)&sk[i * STP + e0 + 4];
            float uu[8] = {ua.x, ua.y, ua.z, ua.w, ub.x, ub.y, ub.z, ub.w};
            float kk[8] = {ka.x, ka.y, ka.z, ka.w, kb.x, kb.y, kb.z, kb.w};
#pragma unroll
            for (int r = 0; r < 8; r++)
#pragma unroll
                for (int c = 0; c < 8; c++)
                    acc[r][c] += uu[r] * kk[c];
        }
        float* Pp = P + ((size_t)bh * NC_ + n) * (D_ * D_);
#pragma unroll
        for (int r = 0; r < 8; r++) {
            float* p = Pp + (size_t)(d0 + r) * 128 + e0;
            *(float4*)(p)     = make_float4(acc[r][0], acc[r][1], acc[r][2], acc[r][3]);
            *(float4*)(p + 4) = make_float4(acc[r][4], acc[r][5], acc[r][6], acc[r][7]);
        }
    }
}

// ---------------------------------------------------------------------------
// Exclusive prefix over chunks of P per (bh); final state -> output tail
// ---------------------------------------------------------------------------
__global__ __launch_bounds__(256) void prefix_state(
    float* __restrict__ P, float* __restrict__ out_state)
{
    int bh = blockIdx.x >> 3;
    int part = blockIdx.x & 7;
    int idx = part * 2048 + threadIdx.x * 8;
    float acc[8] = {0, 0, 0, 0, 0, 0, 0, 0};
    float* base = P + (size_t)bh * NC_ * (D_ * D_) + idx;
    for (int nn = 0; nn < NC_; nn++) {
        float* p = base + (size_t)nn * (D_ * D_);
        float4 p0 = *(float4*)(p);
        float4 p1 = *(float4*)(p + 4);
        *(float4*)(p)     = make_float4(acc[0], acc[1], acc[2], acc[3]);
        *(float4*)(p + 4) = make_float4(acc[4], acc[5], acc[6], acc[7]);
        acc[0] += p0.x; acc[1] += p0.y; acc[2] += p0.z; acc[3] += p0.w;
        acc[4] += p1.x; acc[5] += p1.y; acc[6] += p1.z; acc[7] += p1.w;
    }
    float* q = out_state + (size_t)bh * (D_ * D_) + idx;
    *(float4*)(q)     = make_float4(acc[0], acc[1], acc[2], acc[3]);
    *(float4*)(q + 4) = make_float4(acc[4], acc[5], acc[6], acc[7]);
}

// ---------------------------------------------------------------------------
// Inter-chunk: o[i][d] += sum_e q[i][e] * S_n[d][e]
// ---------------------------------------------------------------------------
#define IN_SMEM ((64 * STP + 128 * STP) * 4)

__global__ __launch_bounds__(256) void inter_chunk(
    const float* __restrict__ q, const float* __restrict__ P,
    float* __restrict__ o)
{
    extern __shared__ float sm[];
    float* sq = sm;
    float* sS = sm + 64 * STP;

    const int n = blockIdx.x, bh = blockIdx.y;
    const int tid = threadIdx.x;
    const size_t qbase = ((size_t)bh * S_ + n * 64) * D_;
    const float* Sp = P + ((size_t)bh * NC_ + n) * (D_ * D_);

    for (int v = tid; v < 64 * 32; v += 256) {
        int r = v >> 5, c4 = (v & 31) * 4;
        *(float4*)&sq[r * STP + c4] = *(const float4*)(q + qbase + r * 128 + c4);
    }
    for (int v = tid; v < 128 * 32; v += 256) {
        int r = v >> 5, c4 = (v & 31) * 4;
        *(float4*)&sS[r * STP + c4] = *(const float4*)(Sp + (size_t)r * 128 + c4);
    }
    __syncthreads();

    int i0 = (tid >> 4) * 4, d0 = (tid & 15) * 8;
    float acc[4][8] = {};
    for (int e = 0; e < 128; e += 4) {
        float4 qv[4];
#pragma unroll
        for (int r = 0; r < 4; r++) qv[r] = *(const float4*)&sq[(i0 + r) * STP + e];
#pragma unroll
        for (int c = 0; c < 8; c++) {
            float4 sv = *(const float4*)&sS[(d0 + c) * STP + e];
#pragma unroll
            for (int r = 0; r < 4; r++)
                acc[r][c] += qv[r].x * sv.x + qv[r].y * sv.y
                           + qv[r].z * sv.z + qv[r].w * sv.w;
        }
    }
    int b = bh >> 4, h = bh & 15;
#pragma unroll
    for (int r = 0; r < 4; r++) {
        float* p = o + (size_t)(b * S_ + n * 64 + i0 + r) * H_ + h * 128 + d0;
        float4 c0 = *(float4*)(p);
        float4 c1 = *(float4*)(p + 4);
        c0.x += acc[r][0]; c0.y += acc[r][1]; c0.z += acc[r][2]; c0.w += acc[r][3];
        c1.x += acc[r][4]; c1.y += acc[r][5]; c1.z += acc[r][6]; c1.w += acc[r][7];
        *(float4*)(p)     = c0;
        *(float4*)(p + 4) = c1;
    }
}

// ---------------------------------------------------------------------------
// Launch
// ---------------------------------------------------------------------------
extern "C" void kernel_launch(void* const* d_in, const int* in_sizes, int n_in,
                              void* d_out, int out_size)
{
    (void)in_sizes; (void)n_in; (void)out_size;
    const float* x  = (const float*)d_in[0];
    const float* Wq = (const float*)d_in[1];
    const float* Wk = (const float*)d_in[2];
    const float* Wv = (const float*)d_in[3];
    const float* Wb = (const float*)d_in[4];
    const float* Wo = (const float*)d_in[5];
    float* out = (float*)d_out;
    float* out_state = out + (size_t)M_ * H_;

    float *pq, *pk, *pu, *pvr, *pbr, *po, *pP;
    __nv_bfloat16 *pxh, *pxl, *poh, *pol, *pWth, *pWtl;
    cudaGetSymbolAddress((void**)&pq,  g_q);
    cudaGetSymbolAddress((void**)&pk,  g_k);
    cudaGetSymbolAddress((void**)&pu,  g_u);
    cudaGetSymbolAddress((void**)&pvr, g_vraw);
    cudaGetSymbolAddress((void**)&pbr, g_braw);
    cudaGetSymbolAddress((void**)&po,  g_o);
    cudaGetSymbolAddress((void**)&pP,  g_P);
    cudaGetSymbolAddress((void**)&pxh, g_xh);
    cudaGetSymbolAddress((void**)&pxl, g_xl);
    cudaGetSymbolAddress((void**)&poh, g_oh);
    cudaGetSymbolAddress((void**)&pol, g_ol);
    cudaGetSymbolAddress((void**)&pWth, g_Wth);
    cudaGetSymbolAddress((void**)&pWtl, g_Wtl);

    cudaFuncSetAttribute(tcgemm<0>, cudaFuncAttributeMaxDynamicSharedMemorySize, GEMM_SMEM);
    cudaFuncSetAttribute(tcgemm<1>, cudaFuncAttributeMaxDynamicSharedMemorySize, GEMM_SMEM);
    cudaFuncSetAttribute(chunk_local, cudaFuncAttributeMaxDynamicSharedMemorySize, CL_SMEM);
    cudaFuncSetAttribute(inter_chunk, cudaFuncAttributeMaxDynamicSharedMemorySize, IN_SMEM);

    const size_t WSZ = (size_t)H_ * H_;
    dim3 tg(H_ / 32, H_ / 32), tb(32, 8);
    transpose_split<<<tg, tb>>>(Wq, pWth + 0 * WSZ, pWtl + 0 * WSZ);
    transpose_split<<<tg, tb>>>(Wk, pWth + 1 * WSZ, pWtl + 1 * WSZ);
    transpose_split<<<tg, tb>>>(Wv, pWth + 2 * WSZ, pWtl + 2 * WSZ);
    transpose_split<<<tg, tb>>>(Wb, pWth + 3 * WSZ, pWtl + 3 * WSZ);
    transpose_split<<<tg, tb>>>(Wo, pWth + 4 * WSZ, pWtl + 4 * WSZ);

    split_convert<<<(M_ * (H_ / 4)) / 256, 256>>>(x, pxh, pxl);

    dim3 gg(H_ / 128, M_ / 128);   // (16, 64)
    tcgemm<1><<<gg, 256, GEMM_SMEM>>>(pxh, pxl, pWth + 0 * WSZ, pWtl + 0 * WSZ, pq);
    tcgemm<1><<<gg, 256, GEMM_SMEM>>>(pxh, pxl, pWth + 1 * WSZ, pWtl + 1 * WSZ, pk);
    tcgemm<0><<<gg, 256, GEMM_SMEM>>>(pxh, pxl, pWth + 2 * WSZ, pWtl + 2 * WSZ, pvr);
    tcgemm<0><<<gg, 256, GEMM_SMEM>>>(pxh, pxl, pWth + 3 * WSZ, pWtl + 3 * WSZ, pbr);

    ewise_u<<<(M_ * H_ / 4) / 256, 256>>>(pvr, pbr, pu);

    dim3 gc(NC_, B_ * NH_);      // (64, 32)
    chunk_local<<<gc, 256, CL_SMEM>>>(pq, pk, pu, po, pP);
    prefix_state<<<B_ * NH_ * 8, 256>>>(pP, out_state);
    inter_chunk<<<gc, 256, IN_SMEM>>>(pq, pP, po);

    split_convert<<<(M_ * (H_ / 4)) / 256, 256>>>(po, poh, pol);
    tcgemm<0><<<gg, 256, GEMM_SMEM>>>(poh, pol, pWth + 4 * WSZ, pWtl + 4 * WSZ, out);
}